// round 9
// baseline (speedup 1.0000x reference)
#include <cuda_runtime.h>
#include <cstdint>

#define B_  64
#define HW_ 4096
#define C_  128      // N
#define P_  64       // K
#define NCHUNK 32
#define TILE_M 128

#define PITCH_A 68    // s-tile smem pitch (floats)
#define PITCH_B 136   // k-tile smem pitch (floats)
#define SMEM_FLOATS (128 * PITCH_A + 2 * P_ * PITCH_B)   // sA + sBh + sBl

// ---------------- scratch ----------------
__device__ float g_zsum[(size_t)B_ * NCHUNK * C_];
__device__ float g_z2[(size_t)B_ * NCHUNK];

// ---------------- helpers ----------------
__device__ __forceinline__ uint32_t tf32_rna(float a) {
    uint32_t r;
    asm("cvt.rna.tf32.f32 %0, %1;" : "=r"(r) : "f"(a));
    return r;
}

__device__ __forceinline__ void mma_tf32(float* d, const uint32_t* a,
                                         uint32_t b0, uint32_t b1) {
    asm volatile(
        "mma.sync.aligned.m16n8k8.row.col.f32.tf32.tf32.f32 "
        "{%0,%1,%2,%3}, {%4,%5,%6,%7}, {%8,%9}, {%0,%1,%2,%3};"
        : "+f"(d[0]), "+f"(d[1]), "+f"(d[2]), "+f"(d[3])
        : "r"(a[0]), "r"(a[1]), "r"(a[2]), "r"(a[3]), "r"(b0), "r"(b1));
}

// ---------------- fused kernel: z-reduce + tf32 GEMM ----------------
__global__ __launch_bounds__(256, 2)
void fused_kernel(const float* __restrict__ z, const float* __restrict__ s,
                  const float* __restrict__ kk, float* __restrict__ out) {
    extern __shared__ float sm[];
    float*    sA  = sm;                                    // [128][PITCH_A]
    uint32_t* sBh = (uint32_t*)(sm + 128 * PITCH_A);       // [P_][PITCH_B]
    uint32_t* sBl = sBh + P_ * PITCH_B;                    // [P_][PITCH_B]

    __shared__ float4 sred[256];
    __shared__ float  sz2[256];

    const int tid  = threadIdx.x;
    const int wid  = tid >> 5;
    const int lane = tid & 31;
    const int bx   = blockIdx.x;
    const size_t m0 = (size_t)bx * TILE_M;

    // ---- stage s tile: 128 rows x 64 floats ----
    #pragma unroll
    for (int i = 0; i < 8; ++i) {
        const int idx = tid + i * 256;
        const int r = idx >> 4, q = idx & 15;
        float4 v = ((const float4*)(s + (m0 + r) * P_))[q];
        *(float4*)(sA + r * PITCH_A + q * 4) = v;
    }
    // ---- stage k split into tf32 hi/lo tiles (converted ONCE per CTA) ----
    #pragma unroll
    for (int i = 0; i < 8; ++i) {
        const int idx = tid + i * 256;
        const int p = idx >> 5, q = idx & 31;
        float4 v = ((const float4*)(kk + (size_t)p * C_))[q];
        uint4 h, l;
        h.x = tf32_rna(v.x); l.x = tf32_rna(v.x - __uint_as_float(h.x));
        h.y = tf32_rna(v.y); l.y = tf32_rna(v.y - __uint_as_float(h.y));
        h.z = tf32_rna(v.z); l.z = tf32_rna(v.z - __uint_as_float(h.z));
        h.w = tf32_rna(v.w); l.w = tf32_rna(v.w - __uint_as_float(h.w));
        *(uint4*)(sBh + p * PITCH_B + q * 4) = h;
        *(uint4*)(sBl + p * PITCH_B + q * 4) = l;
    }

    // ---- z reduction phase ----
    {
        const int b     = bx >> 5;
        const int chunk = bx & 31;
        const float4* base =
            (const float4*)(z + ((size_t)b * HW_ + (size_t)chunk * 128) * C_);
        const int cq = tid & 31;
        const int rg = tid >> 5;

        float4 acc = make_float4(0.f, 0.f, 0.f, 0.f);
        float z2 = 0.f;
        #pragma unroll
        for (int j = 0; j < 16; ++j) {
            float4 v = base[(size_t)(rg + 8 * j) * (C_ / 4) + cq];
            acc.x += v.x; acc.y += v.y; acc.z += v.z; acc.w += v.w;
            z2 += v.x * v.x + v.y * v.y + v.z * v.z + v.w * v.w;
        }
        // warp-level z2 reduce first (no barriers)
        #pragma unroll
        for (int off = 16; off > 0; off >>= 1)
            z2 += __shfl_down_sync(0xffffffffu, z2, off);
        sred[tid] = acc;
        if (lane == 0) sz2[rg] = z2;
        __syncthreads();

        if (rg == 0) {
            float4 t = sred[cq];
            #pragma unroll
            for (int g = 1; g < 8; ++g) {
                float4 v = sred[g * 32 + cq];
                t.x += v.x; t.y += v.y; t.z += v.z; t.w += v.w;
            }
            ((float4*)(g_zsum + ((size_t)b * NCHUNK + chunk) * C_))[cq] = t;
            if (cq == 0) {
                float tt = 0.f;
                #pragma unroll
                for (int g = 0; g < 8; ++g) tt += sz2[g];
                g_z2[(size_t)b * NCHUNK + chunk] = tt;
            }
        }
    }
    __syncthreads();

    // ---- MMA phase: warp grid 4(M) x 2(N); warp tile 32x64 ----
    const int warpM = wid & 3;
    const int warpN = wid >> 2;
    const int lq = lane >> 2;   // 0..7
    const int lr = lane & 3;    // 0..3

    float acc[2][8][4];
    #pragma unroll
    for (int mi = 0; mi < 2; ++mi)
        #pragma unroll
        for (int ni = 0; ni < 8; ++ni)
            #pragma unroll
            for (int j = 0; j < 4; ++j) acc[mi][ni][j] = 0.f;

    #pragma unroll
    for (int k0 = 0; k0 < P_; k0 += 8) {
        uint32_t ah[2][4], al[2][4];
        #pragma unroll
        for (int mi = 0; mi < 2; ++mi) {
            const int r = warpM * 32 + mi * 16 + lq;
            const float* base = sA + r * PITCH_A + k0 + lr;
            const float a0 = base[0];
            const float a1 = base[8 * PITCH_A];
            const float a2 = base[4];
            const float a3 = base[8 * PITCH_A + 4];
            ah[mi][0] = tf32_rna(a0); al[mi][0] = tf32_rna(a0 - __uint_as_float(ah[mi][0]));
            ah[mi][1] = tf32_rna(a1); al[mi][1] = tf32_rna(a1 - __uint_as_float(ah[mi][1]));
            ah[mi][2] = tf32_rna(a2); al[mi][2] = tf32_rna(a2 - __uint_as_float(ah[mi][2]));
            ah[mi][3] = tf32_rna(a3); al[mi][3] = tf32_rna(a3 - __uint_as_float(ah[mi][3]));
        }
        #pragma unroll
        for (int ni = 0; ni < 8; ++ni) {
            const int c = warpN * 64 + ni * 8 + lq;
            const uint32_t* bhp = sBh + (k0 + lr) * PITCH_B + c;
            const uint32_t* blp = sBl + (k0 + lr) * PITCH_B + c;
            const uint32_t bh0 = bhp[0];
            const uint32_t bh1 = bhp[4 * PITCH_B];
            const uint32_t bl0 = blp[0];
            const uint32_t bl1 = blp[4 * PITCH_B];
            #pragma unroll
            for (int mi = 0; mi < 2; ++mi) {
                mma_tf32(acc[mi][ni], ah[mi], bh0, bh1);  // hi*hi
                mma_tf32(acc[mi][ni], ah[mi], bl0, bl1);  // hi*lo
                mma_tf32(acc[mi][ni], al[mi], bh0, bh1);  // lo*hi
            }
        }
    }

    // ---- epilogue ----
    #pragma unroll
    for (int mi = 0; mi < 2; ++mi) {
        const size_t row = m0 + warpM * 32 + mi * 16 + lq;
        #pragma unroll
        for (int ni = 0; ni < 8; ++ni) {
            const int col = warpN * 64 + ni * 8 + 2 * lr;
            *(float2*)(out + row * C_ + col) =
                make_float2(acc[mi][ni][0], acc[mi][ni][1]);
            *(float2*)(out + (row + 8) * C_ + col) =
                make_float2(acc[mi][ni][2], acc[mi][ni][3]);
        }
    }
}

// ---------------- Kernel 2: distance (parallelized) ----------------
// grid B_, block 256
__global__ __launch_bounds__(256)
void dist_kernel(const float* __restrict__ kk, float* __restrict__ dist) {
    const int b = blockIdx.x;
    const int tid = threadIdx.x;
    __shared__ float part[2][C_];
    __shared__ float zs[C_];
    __shared__ float z2s;

    // phase 1: zsum chunk reduction, split across 2 halves (16-deep chains)
    {
        const int c    = tid & 127;
        const int half = tid >> 7;
        const float* base = g_zsum + ((size_t)b * NCHUNK + half * 16) * C_ + c;
        float a = 0.f;
        #pragma unroll
        for (int ch = 0; ch < 16; ++ch) a += base[(size_t)ch * C_];
        part[half][c] = a;
    }
    // z2 reduce (warp 0)
    if (tid < 32) {
        float t = g_z2[(size_t)b * NCHUNK + tid];
        #pragma unroll
        for (int off = 16; off > 0; off >>= 1)
            t += __shfl_down_sync(0xffffffffu, t, off);
        if (tid == 0) z2s = t;
    }
    __syncthreads();
    if (tid < C_) zs[tid] = part[0][tid] + part[1][tid];
    __syncthreads();

    // phase 2: dist — 4 threads per p, each covers 32 c's
    {
        const int p   = tid >> 2;
        const int sub = tid & 3;
        const float* kp = kk + (size_t)p * C_ + sub * 32;
        const float* zp = zs + sub * 32;
        float dot = 0.f, k2 = 0.f;
        #pragma unroll
        for (int c = 0; c < 32; ++c) {
            const float kv = kp[c];
            dot += zp[c] * kv;
            k2  += kv * kv;
        }
        dot += __shfl_xor_sync(0xffffffffu, dot, 1);
        k2  += __shfl_xor_sync(0xffffffffu, k2, 1);
        dot += __shfl_xor_sync(0xffffffffu, dot, 2);
        k2  += __shfl_xor_sync(0xffffffffu, k2, 2);
        if (sub == 0)
            dist[(size_t)b * P_ + p] = z2s - 2.f * dot + (float)HW_ * k2;
    }
}

// ---------------- launch ----------------
extern "C" void kernel_launch(void* const* d_in, const int* in_sizes, int n_in,
                              void* d_out, int out_size) {
    const float* z = (const float*)d_in[0];
    const float* s = (const float*)d_in[1];
    const float* k = (const float*)d_in[2];
    float* out  = (float*)d_out;
    float* dist = out + (size_t)in_sizes[0];

    static bool attr_set = false;
    if (!attr_set) {
        cudaFuncSetAttribute(fused_kernel,
                             cudaFuncAttributeMaxDynamicSharedMemorySize,
                             SMEM_FLOATS * (int)sizeof(float));
        attr_set = true;
    }

    fused_kernel<<<(B_ * HW_) / TILE_M, 256, SMEM_FLOATS * sizeof(float)>>>(
        z, s, k, out);
    dist_kernel<<<B_, 256>>>(k, dist);
}